// round 8
// baseline (speedup 1.0000x reference)
#include <cuda_runtime.h>
#include <cstdint>
#include <cstddef>

#define Bn   2
#define Ln   2048
#define Hn   768
#define DIn  1536
#define Nn   16
#define Rn   48
#define BLn  (Bn*Ln)     /* 4096 */
#define SP   (Rn + 2*Nn) /* 80 */

// -------- scratch (static device globals; no allocation allowed) --------
__device__ float g_proj [(size_t)BLn * 2 * DIn];  // in_proj output (h | gate)
__device__ float g_h    [(size_t)BLn * DIn];      // conv+silu output
__device__ float g_ssm  [(size_t)BLn * SP];       // x_proj output (dt_raw|B|C)
__device__ float g_dtraw[(size_t)BLn * Rn];       // tf32-rounded dt_raw copy
__device__ float g_dt   [(size_t)BLn * DIn];      // softplus(dt)
__device__ float g_y    [(size_t)BLn * DIn];      // scan output (tf32-rounded)
__device__ float g_xr   [(size_t)BLn * Hn];       // tf32-rounded x
__device__ float g_w1   [(size_t)Hn * 2 * DIn];   // in_proj_w^T  [3072][768], tf32
__device__ float g_w2   [(size_t)Rn * DIn];       // dt_proj_w^T  [1536][48],  tf32
__device__ float g_w3   [(size_t)DIn * Hn];       // out_proj_w^T [768][1536], tf32

__device__ __forceinline__ float sigmoidf_(float x) { return 1.f / (1.f + __expf(-x)); }
__device__ __forceinline__ uint32_t f2tf(float f) {
    uint32_t u; asm("cvt.rna.tf32.f32 %0, %1;" : "=r"(u) : "f"(f)); return u;
}
__device__ __forceinline__ float roundtf(float f) { return __uint_as_float(f2tf(f)); }
__device__ __forceinline__ float softplusf_(float x) {
    return fmaxf(x, 0.f) + log1pf(__expf(-fabsf(x)));
}
__device__ __forceinline__ void cp16s(uint32_t sa, const void* g) {
    asm volatile("cp.async.cg.shared.global [%0], [%1], 16;\n" :: "r"(sa), "l"(g));
}
__device__ __forceinline__ void cp_commit() {
    asm volatile("cp.async.commit_group;\n");
}
template<int NN>
__device__ __forceinline__ void cp_wait() {
    asm volatile("cp.async.wait_group %0;\n" :: "n"(NN));
}
__device__ __forceinline__ uint32_t smem_u32(const void* p) {
    return (uint32_t)__cvta_generic_to_shared(p);
}
__device__ __forceinline__ void ldsm_x4(uint32_t& r0, uint32_t& r1, uint32_t& r2,
                                        uint32_t& r3, uint32_t a) {
    asm volatile("ldmatrix.sync.aligned.m8n8.x4.shared.b16 {%0,%1,%2,%3}, [%4];"
                 : "=r"(r0), "=r"(r1), "=r"(r2), "=r"(r3) : "r"(a));
}

// ============================================================================
// preround: tf32-round x (float4 grid-stride).
// ============================================================================
#define S0 ((size_t)BLn * Hn)
__global__ __launch_bounds__(256)
void preround(const float* __restrict__ x)
{
    size_t i = ((size_t)blockIdx.x * blockDim.x + threadIdx.x) * 4;
    if (i >= S0) return;
    float4 v = *(const float4*)(x + i);
    v.x = roundtf(v.x); v.y = roundtf(v.y); v.z = roundtf(v.z); v.w = roundtf(v.w);
    *(float4*)(g_xr + i) = v;
}

// dst[c][r] = round_tf32(src[r][c]); src [R][C] -> dst [C][R]. Bounds-guarded.
__global__ __launch_bounds__(256)
void transpose_round(const float* __restrict__ src, float* __restrict__ dst,
                     int R, int C)
{
    __shared__ float t[32][33];
    const int bx = blockIdx.x << 5;
    const int by = blockIdx.y << 5;
    const int tx = threadIdx.x & 31;
    const int ty = threadIdx.x >> 5;
#pragma unroll
    for (int i = 0; i < 32; i += 8) {
        int r = by + ty + i, c = bx + tx;
        if (r < R && c < C) t[ty + i][tx] = src[(size_t)r * C + c];
    }
    __syncthreads();
#pragma unroll
    for (int i = 0; i < 32; i += 8) {
        int r = bx + ty + i, c = by + tx;
        if (r < C && c < R) dst[(size_t)r * R + c] = roundtf(t[tx][ty + i]);
    }
}

__global__ __launch_bounds__(256)
void zero_ssm()
{
    size_t i = ((size_t)blockIdx.x * blockDim.x + threadIdx.x) * 4;
    if (i < (size_t)BLn * SP) *(float4*)&g_ssm[i] = make_float4(0.f, 0.f, 0.f, 0.f);
}

__global__ __launch_bounds__(256)
void round_dtraw()
{
    int i = blockIdx.x * blockDim.x + threadIdx.x;
    if (i >= BLn * Rn) return;
    int row = i / Rn, col = i - row * Rn;
    g_dtraw[i] = roundtf(g_ssm[(size_t)row * SP + col]);
}

// ============================================================================
// TF32 mma.sync GEMM, 128x256 CTA tile, 8 warps of 64x64, ldmatrix x4,
// 4-stage cp.async.  C[M,N] = A[M,K](lda) @ Bt[N,K](ldb)^T.
// A,Bt pre-rounded tf32. EPI==1: C = softplus(C + bias[n]).
// smem/stage: A[128][20] + B[256][20] floats = 30720 B; 4 stages = 122880 B.
// ============================================================================
#define TG_STAGES 4
#define TG_ASZ (128 * 20)
#define TG_BSZ (256 * 20)
#define TG_STG (TG_ASZ + TG_BSZ)
#define TG_SMEM (TG_STAGES * TG_STG * 4)

template<int EPI>
__global__ __launch_bounds__(256, 1)
void tgemm(const float* __restrict__ A, int lda,
           const float* __restrict__ Bt, int ldb,
           float* __restrict__ C, int N, int K,
           const float* __restrict__ bias)
{
    extern __shared__ float smem[];

    const int tid  = threadIdx.x;
    const int lane = tid & 31;
    const int warp = tid >> 5;
    const int wm   = warp >> 2;        // 0..1
    const int wn   = warp & 3;         // 0..3
    const int m0   = wm * 64;
    const int n0   = wn * 64;
    const int g    = lane >> 2;
    const int c    = lane & 3;

    const int bm = blockIdx.y << 7;
    const int bn = blockIdx.x << 8;

    const uint32_t smem0 = smem_u32(smem);

    // A cp.async: 512 chunks of 16B, 2/thread
    const int chA = tid * 2;
    const int rA0 = chA >> 2,       kA0 = (chA & 3) << 2;
    const int rA1 = (chA + 1) >> 2, kA1 = ((chA + 1) & 3) << 2;
    const float* ApA = A + (size_t)(bm + rA0) * lda + kA0;
    const float* ApB = A + (size_t)(bm + rA1) * lda + kA1;
    const uint32_t sAo0 = (uint32_t)(rA0 * 20 + kA0) * 4;
    const uint32_t sAo1 = (uint32_t)(rA1 * 20 + kA1) * 4;
    // B cp.async: 1024 chunks, 4/thread = one full row (k=0..15) per thread
    const float* Bp = Bt + (size_t)(bn + tid) * ldb;
    const uint32_t sBrow = (uint32_t)(tid * 20) * 4;

    // ldmatrix bases
    // A x4: m0..m3 = (rows 0-7,kc),(rows 8-15,kc),(rows 0-7,kc+4),(rows 8-15,kc+4)
    const int arow = m0 + (lane & 7) + ((lane & 8) ? 8 : 0);
    const int acol = (lane & 16) ? 4 : 0;
    const uint32_t aBase = (uint32_t)(arow * 20 + acol) * 4;
    // B x4: m0..m3 = (rows j8,kc),(rows j8,kc+4),(rows j8+8,kc),(rows j8+8,kc+4)
    const int brow = n0 + (lane & 7) + ((lane & 16) ? 8 : 0);
    const int bcol = (lane & 8) ? 4 : 0;
    const uint32_t bBase = (uint32_t)(brow * 20 + bcol) * 4;

    float acc[4][8][4];
#pragma unroll
    for (int i = 0; i < 4; i++)
#pragma unroll
        for (int j = 0; j < 8; j++)
#pragma unroll
            for (int q = 0; q < 4; q++) acc[i][j][q] = 0.f;

    const int nk = K >> 4;

    auto load_stage = [&](int kt, int s) {
        const uint32_t st = smem0 + (uint32_t)(s * TG_STG) * 4;
        const uint32_t stB = st + TG_ASZ * 4;
        const int k0 = kt << 4;
        cp16s(st + sAo0, ApA + k0);
        cp16s(st + sAo1, ApB + k0);
#pragma unroll
        for (int j = 0; j < 4; j++)
            cp16s(stB + sBrow + (uint32_t)(j * 4) * 4, Bp + k0 + j * 4);
    };
    auto compute = [&](int s) {
        const uint32_t stA = smem0 + (uint32_t)(s * TG_STG) * 4;
        const uint32_t stB = stA + TG_ASZ * 4;
#pragma unroll
        for (int ks = 0; ks < 2; ks++) {
            const uint32_t kb = (uint32_t)(ks << 3) * 4;
            uint32_t af[4][4], bf[8][2];
#pragma unroll
            for (int i = 0; i < 4; i++)
                ldsm_x4(af[i][0], af[i][1], af[i][2], af[i][3],
                        stA + aBase + (uint32_t)(i * 16 * 20) * 4 + kb);
#pragma unroll
            for (int jj = 0; jj < 4; jj++)
                ldsm_x4(bf[2 * jj][0], bf[2 * jj][1], bf[2 * jj + 1][0], bf[2 * jj + 1][1],
                        stB + bBase + (uint32_t)(jj * 16 * 20) * 4 + kb);
#pragma unroll
            for (int i = 0; i < 4; i++)
#pragma unroll
                for (int j = 0; j < 8; j++)
                    asm volatile(
                        "mma.sync.aligned.m16n8k8.row.col.f32.tf32.tf32.f32 "
                        "{%0,%1,%2,%3}, {%4,%5,%6,%7}, {%8,%9}, {%0,%1,%2,%3};\n"
                        : "+f"(acc[i][j][0]), "+f"(acc[i][j][1]),
                          "+f"(acc[i][j][2]), "+f"(acc[i][j][3])
                        : "r"(af[i][0]), "r"(af[i][1]), "r"(af[i][2]), "r"(af[i][3]),
                          "r"(bf[j][0]), "r"(bf[j][1]));
        }
    };

#pragma unroll
    for (int s = 0; s < TG_STAGES - 1; s++) {
        if (s < nk) load_stage(s, s);
        cp_commit();
    }
    for (int kt = 0; kt < nk; ++kt) {
        cp_wait<TG_STAGES - 2>();
        __syncthreads();
        const int nxt = kt + TG_STAGES - 1;
        if (nxt < nk) load_stage(nxt, nxt & (TG_STAGES - 1));
        cp_commit();
        compute(kt & (TG_STAGES - 1));
    }

    // epilogue
#pragma unroll
    for (int i = 0; i < 4; i++) {
        const int r0 = bm + m0 + i * 16 + g;
#pragma unroll
        for (int j = 0; j < 8; j++) {
            const int col = bn + n0 + j * 8 + 2 * c;
            float v00 = acc[i][j][0], v01 = acc[i][j][1];
            float v10 = acc[i][j][2], v11 = acc[i][j][3];
            if (EPI == 1) {
                const float b0v = bias[col], b1v = bias[col + 1];
                v00 = softplusf_(v00 + b0v);
                v01 = softplusf_(v01 + b1v);
                v10 = softplusf_(v10 + b0v);
                v11 = softplusf_(v11 + b1v);
            }
            *(float2*)&C[(size_t)r0 * N + col]       = make_float2(v00, v01);
            *(float2*)&C[(size_t)(r0 + 8) * N + col] = make_float2(v10, v11);
        }
    }
}

// ============================================================================
// Depthwise causal conv (K=4) + bias + SiLU, 4 channels/thread.
// ============================================================================
__global__ __launch_bounds__(256)
void conv_silu(const float* __restrict__ proj,
               const float* __restrict__ cw,
               const float* __restrict__ cb,
               float* __restrict__ h)
{
    int idx = blockIdx.x * blockDim.x + threadIdx.x;
    int d4 = (idx % (DIn / 4)) << 2;
    int bt = idx / (DIn / 4);
    int t  = bt % Ln;

    const float* p = proj + (size_t)bt * (2 * DIn) + d4;
    const int s = 2 * DIn;
    float4 z  = make_float4(0.f, 0.f, 0.f, 0.f);
    float4 x0 = *(const float4*)p;
    float4 x1 = (t >= 1) ? *(const float4*)(p - s)     : z;
    float4 x2 = (t >= 2) ? *(const float4*)(p - 2 * s) : z;
    float4 x3 = (t >= 3) ? *(const float4*)(p - 3 * s) : z;
    float4 cbv = *(const float4*)(cb + d4);
    float4 w0 = *(const float4*)(cw + (d4 + 0) * 4);
    float4 w1 = *(const float4*)(cw + (d4 + 1) * 4);
    float4 w2 = *(const float4*)(cw + (d4 + 2) * 4);
    float4 w3 = *(const float4*)(cw + (d4 + 3) * 4);

    float4 o;
    o.x = fmaf(x3.x, w0.x, fmaf(x2.x, w0.y, fmaf(x1.x, w0.z, fmaf(x0.x, w0.w, cbv.x))));
    o.y = fmaf(x3.y, w1.x, fmaf(x2.y, w1.y, fmaf(x1.y, w1.z, fmaf(x0.y, w1.w, cbv.y))));
    o.z = fmaf(x3.z, w2.x, fmaf(x2.z, w2.y, fmaf(x1.z, w2.z, fmaf(x0.z, w2.w, cbv.z))));
    o.w = fmaf(x3.w, w3.x, fmaf(x2.w, w3.y, fmaf(x1.w, w3.z, fmaf(x0.w, w3.w, cbv.w))));
    o.x = o.x * sigmoidf_(o.x);
    o.y = o.y * sigmoidf_(o.y);
    o.z = o.z * sigmoidf_(o.z);
    o.w = o.w * sigmoidf_(o.w);
    *(float4*)(h + (size_t)bt * DIn + d4) = o;
}

// ============================================================================
// x_proj GEMM, split-K: ssm += h @ x_proj_w.
// ============================================================================
#define XKS 4
#define XKC (DIn / XKS)
__global__ __launch_bounds__(256)
void gemm_xproj(const float* __restrict__ A,
                const float* __restrict__ W)
{
    __shared__ float As[2][16][68];
    __shared__ float Ws[2][16][SP];

    const int tid = threadIdx.x;
    const int bm  = blockIdx.x << 6;
    const int k0  = blockIdx.y * XKC;
    const int tx  = tid & 15;
    const int ty  = tid >> 4;
    const int ar  = tid >> 2;
    const int ac4 = (tid & 3) << 2;

    float acc[4][5];
#pragma unroll
    for (int i = 0; i < 4; i++)
#pragma unroll
        for (int j = 0; j < 5; j++) acc[i][j] = 0.f;

    const float* Ap = A + (size_t)(bm + ar) * DIn + k0 + ac4;
    const int nk = XKC / 16;

    float4 aR; float wR[5];
    auto g2r = [&](int kt) {
        aR = *(const float4*)(Ap + kt * 16);
#pragma unroll
        for (int j = 0; j < 5; j++) {
            int e = tid + (j << 8);
            int k = e / SP, n2 = e % SP;
            wR[j] = W[(size_t)(k0 + kt * 16 + k) * SP + n2];
        }
    };
    auto r2s = [&](int buf) {
        As[buf][ac4 + 0][ar] = aR.x;
        As[buf][ac4 + 1][ar] = aR.y;
        As[buf][ac4 + 2][ar] = aR.z;
        As[buf][ac4 + 3][ar] = aR.w;
#pragma unroll
        for (int j = 0; j < 5; j++) {
            int e = tid + (j << 8);
            int k = e / SP, n2 = e % SP;
            Ws[buf][k][n2] = wR[j];
        }
    };

    g2r(0); r2s(0);
    __syncthreads();

    for (int kt = 0; kt < nk; ++kt) {
        const int buf = kt & 1;
        const bool more = (kt + 1 < nk);
        if (more) g2r(kt + 1);
#pragma unroll
        for (int k = 0; k < 16; k++) {
            float4 a4 = *(const float4*)&As[buf][k][ty << 2];
            float av[4] = {a4.x, a4.y, a4.z, a4.w};
#pragma unroll
            for (int j = 0; j < 5; j++) {
                float w = Ws[buf][k][tx * 5 + j];
#pragma unroll
                for (int i = 0; i < 4; i++)
                    acc[i][j] = fmaf(av[i], w, acc[i][j]);
            }
        }
        if (more) r2s(buf ^ 1);
        __syncthreads();
    }

#pragma unroll
    for (int i = 0; i < 4; i++) {
        const int row = bm + (ty << 2) + i;
#pragma unroll
        for (int j = 0; j < 5; j++)
            atomicAdd(&g_ssm[(size_t)row * SP + tx * 5 + j], acc[i][j]);
    }
}

// ============================================================================
// Fused selective scan + skip + gating. 8-timestep batched shuffle reduction.
// ============================================================================
__global__ __launch_bounds__(128)
void scan_kernel(const float* __restrict__ Alog, const float* __restrict__ Dp)
{
    __shared__ float s_h [2][32][8];
    __shared__ float s_dt[2][32][8];
    __shared__ float s_g [2][32][8];
    __shared__ float s_B [2][32][16];
    __shared__ float s_C [2][32][16];

    const int tid  = threadIdx.x;
    const int lane = tid & 31;
    const int w    = tid >> 5;
    const int n    = lane & 15;
    const int half = lane >> 4;
    const int dl   = (w << 1) + half;
    const int blk  = blockIdx.x;
    const int b    = blk / (DIn / 8);
    const int d0   = (blk % (DIn / 8)) << 3;
    const int d    = d0 + dl;
    const int bL   = b * Ln;

    const float A_dn = -__expf(Alog[d * Nn + n]);
    const float Dv   = Dp[d];
    float state = 0.f;

    float rh[2], rdt[2], rg[2], rB[4], rC[4];

    auto do_load = [&](int c) {
        int t0 = c << 5;
#pragma unroll
        for (int j = 0; j < 2; j++) {
            int e = tid + (j << 7);
            int t = e >> 3, dd = e & 7;
            int row = bL + t0 + t;
            rh[j]  = g_h [(size_t)row * DIn + d0 + dd];
            rdt[j] = g_dt[(size_t)row * DIn + d0 + dd];
            rg[j]  = g_proj[(size_t)row * (2 * DIn) + DIn + d0 + dd];
        }
#pragma unroll
        for (int j = 0; j < 4; j++) {
            int e = tid + (j << 7);
            int t = e >> 4, nn = e & 15;
            int row = bL + t0 + t;
            rB[j] = g_ssm[(size_t)row * SP + Rn + nn];
            rC[j] = g_ssm[(size_t)row * SP + Rn + Nn + nn];
        }
    };
    auto do_store = [&](int buf) {
#pragma unroll
        for (int j = 0; j < 2; j++) {
            int e = tid + (j << 7);
            int t = e >> 3, dd = e & 7;
            s_h [buf][t][dd] = rh[j];
            s_dt[buf][t][dd] = rdt[j];
            s_g [buf][t][dd] = rg[j];
        }
#pragma unroll
        for (int j = 0; j < 4; j++) {
            int e = tid + (j << 7);
            int t = e >> 4, nn = e & 15;
            s_B[buf][t][nn] = rB[j];
            s_C[buf][t][nn] = rC[j];
        }
    };

    do_load(0);
    do_store(0);
    __syncthreads();

    const int NC = Ln / 32;
    for (int c = 0; c < NC; c++) {
        const int buf = c & 1;
        if (c + 1 < NC) do_load(c + 1);
        const int t0 = c << 5;
#pragma unroll
        for (int tb = 0; tb < 32; tb += 8) {
            float p[8], hs[8];
#pragma unroll
            for (int tt = 0; tt < 8; tt++) {
                const int t = tb + tt;
                float dtv = s_dt[buf][t][dl];
                float hv  = s_h [buf][t][dl];
                float Bv  = s_B [buf][t][n];
                float Cv  = s_C [buf][t][n];
                float dA  = __expf(A_dn * dtv);
                state = fmaf(dA, state, Bv * hv);
                p[tt]  = state * Cv;
                hs[tt] = hv;
            }
#pragma unroll
            for (int st = 8; st >= 1; st >>= 1)
#pragma unroll
                for (int tt = 0; tt < 8; tt++)
                    p[tt] += __shfl_xor_sync(0xffffffffu, p[tt], st);
            if (n == 0) {
#pragma unroll
                for (int tt = 0; tt < 8; tt++) {
                    const int t = tb + tt;
                    float gv = s_g[buf][t][dl];
                    float yv = (p[tt] + hs[tt] * Dv) * gv * sigmoidf_(gv);
                    g_y[(size_t)(bL + t0 + t) * DIn + d] = roundtf(yv);
                }
            }
        }
        if (c + 1 < NC) do_store(buf ^ 1);
        __syncthreads();
    }
}

// ============================================================================
extern "C" void kernel_launch(void* const* d_in, const int* in_sizes, int n_in,
                              void* d_out, int out_size)
{
    const float* x          = (const float*)d_in[0];
    const float* in_proj_w  = (const float*)d_in[1];
    const float* conv_w     = (const float*)d_in[2];
    const float* conv_b     = (const float*)d_in[3];
    const float* x_proj_w   = (const float*)d_in[4];
    const float* dt_proj_w  = (const float*)d_in[5];
    const float* dt_proj_b  = (const float*)d_in[6];
    const float* out_proj_w = (const float*)d_in[7];
    const float* A_log      = (const float*)d_in[8];
    const float* D_param    = (const float*)d_in[9];
    float* out = (float*)d_out;

    float *proj, *h, *dtraw, *dt, *y, *xr, *w1t, *w2t, *w3t;
    cudaGetSymbolAddress((void**)&proj,  g_proj);
    cudaGetSymbolAddress((void**)&h,     g_h);
    cudaGetSymbolAddress((void**)&dtraw, g_dtraw);
    cudaGetSymbolAddress((void**)&dt,    g_dt);
    cudaGetSymbolAddress((void**)&y,     g_y);
    cudaGetSymbolAddress((void**)&xr,    g_xr);
    cudaGetSymbolAddress((void**)&w1t,   g_w1);
    cudaGetSymbolAddress((void**)&w2t,   g_w2);
    cudaGetSymbolAddress((void**)&w3t,   g_w3);

    cudaFuncSetAttribute(tgemm<0>, cudaFuncAttributeMaxDynamicSharedMemorySize, TG_SMEM);
    cudaFuncSetAttribute(tgemm<1>, cudaFuncAttributeMaxDynamicSharedMemorySize, TG_SMEM);

    // 0) pre-round x; transpose+round w1, w2, w3; zero split-K accumulator
    preround<<<(unsigned)((S0 / 4 + 255) / 256), 256>>>(x);
    transpose_round<<<dim3((2 * DIn) / 32, Hn / 32), 256>>>(in_proj_w,  w1t, Hn, 2 * DIn);
    transpose_round<<<dim3(DIn / 32, (Rn + 31) / 32), 256>>>(dt_proj_w, w2t, Rn, DIn);
    transpose_round<<<dim3(Hn / 32, DIn / 32), 256>>>(out_proj_w, w3t, DIn, Hn);
    zero_ssm<<<(BLn * SP / 4 + 255) / 256, 256>>>();

    // 1) proj = x @ in_proj_w   [4096,3072], K=768
    tgemm<0><<<dim3((2 * DIn) / 256, BLn / 128), 256, TG_SMEM>>>(
        xr, Hn, w1t, Hn, proj, 2 * DIn, Hn, nullptr);

    // 2) depthwise causal conv + SiLU -> g_h
    conv_silu<<<(BLn * DIn / 4) / 256, 256>>>(proj, conv_w, conv_b, h);

    // 3) ssm += h @ x_proj_w   [4096,80] split-K
    gemm_xproj<<<dim3(BLn / 64, XKS), 256>>>(h, x_proj_w);
    round_dtraw<<<(BLn * Rn + 255) / 256, 256>>>();

    // 4) dt = softplus(dt_raw @ dt_proj_w + b)   [4096,1536], K=48
    tgemm<1><<<dim3(DIn / 256, BLn / 128), 256, TG_SMEM>>>(
        dtraw, Rn, w2t, Rn, dt, DIn, Rn, dt_proj_b);

    // 5) selective scan (+ skip + gating)
    scan_kernel<<<Bn * (DIn / 8), 128>>>(A_log, D_param);

    // 6) out = y @ out_proj_w   [4096,768], K=1536
    tgemm<0><<<dim3(Hn / 256, BLn / 128), 256, TG_SMEM>>>(
        y, DIn, w3t, DIn, out, Hn, DIn, nullptr);
}

// round 9
// speedup vs baseline: 1.1971x; 1.1971x over previous
#include <cuda_runtime.h>
#include <cstdint>
#include <cstddef>

#define Bn   2
#define Ln   2048
#define Hn   768
#define DIn  1536
#define Nn   16
#define Rn   48
#define RnP  64          /* dt K padded to 64 for BK=32 */
#define BLn  (Bn*Ln)     /* 4096 */
#define SP   (Rn + 2*Nn) /* 80 */

// -------- scratch (static device globals; zero-initialized at load) --------
__device__ float g_proj [(size_t)BLn * 2 * DIn];  // in_proj output (h | gate)
__device__ float g_h    [(size_t)BLn * DIn];      // conv+silu output
__device__ float g_ssm  [(size_t)BLn * SP];       // x_proj output (dt_raw|B|C)
__device__ float g_dtraw[(size_t)BLn * RnP];      // tf32 dt_raw, K-padded (cols 48..63 stay 0)
__device__ float g_dt   [(size_t)BLn * DIn];      // softplus(dt)
__device__ float g_y    [(size_t)BLn * DIn];      // scan output (tf32-rounded)
__device__ float g_xr   [(size_t)BLn * Hn];       // tf32-rounded x
__device__ float g_w1   [(size_t)Hn * 2 * DIn];   // in_proj_w^T  [3072][768], tf32
__device__ float g_w2   [(size_t)DIn * RnP];      // dt_proj_w^T  [1536][64],  tf32 (pad 0)
__device__ float g_w3   [(size_t)DIn * Hn];       // out_proj_w^T [768][1536], tf32

__device__ __forceinline__ float sigmoidf_(float x) { return 1.f / (1.f + __expf(-x)); }
__device__ __forceinline__ uint32_t f2tf(float f) {
    uint32_t u; asm("cvt.rna.tf32.f32 %0, %1;" : "=r"(u) : "f"(f)); return u;
}
__device__ __forceinline__ float roundtf(float f) { return __uint_as_float(f2tf(f)); }
__device__ __forceinline__ float softplusf_(float x) {
    return fmaxf(x, 0.f) + log1pf(__expf(-fabsf(x)));
}
__device__ __forceinline__ void cp16s(uint32_t sa, const void* g) {
    asm volatile("cp.async.cg.shared.global [%0], [%1], 16;\n" :: "r"(sa), "l"(g));
}
__device__ __forceinline__ void cp_commit() {
    asm volatile("cp.async.commit_group;\n");
}
template<int NN>
__device__ __forceinline__ void cp_wait() {
    asm volatile("cp.async.wait_group %0;\n" :: "n"(NN));
}
__device__ __forceinline__ uint32_t smem_u32(const void* p) {
    return (uint32_t)__cvta_generic_to_shared(p);
}
__device__ __forceinline__ void ldsm_x4(uint32_t& r0, uint32_t& r1, uint32_t& r2,
                                        uint32_t& r3, uint32_t a) {
    asm volatile("ldmatrix.sync.aligned.m8n8.x4.shared.b16 {%0,%1,%2,%3}, [%4];"
                 : "=r"(r0), "=r"(r1), "=r"(r2), "=r"(r3) : "r"(a));
}

// ============================================================================
// preround: tf32-round x (float4 grid-stride).
// ============================================================================
#define S0 ((size_t)BLn * Hn)
__global__ __launch_bounds__(256)
void preround(const float* __restrict__ x)
{
    size_t i = ((size_t)blockIdx.x * blockDim.x + threadIdx.x) * 4;
    if (i >= S0) return;
    float4 v = *(const float4*)(x + i);
    v.x = roundtf(v.x); v.y = roundtf(v.y); v.z = roundtf(v.z); v.w = roundtf(v.w);
    *(float4*)(g_xr + i) = v;
}

// dst[c][r] = round_tf32(src[r][c]); src [R][C] -> dst [C][Rstride] (row stride Rstride).
__global__ __launch_bounds__(256)
void transpose_round(const float* __restrict__ src, float* __restrict__ dst,
                     int R, int C, int Rstride)
{
    __shared__ float t[32][33];
    const int bx = blockIdx.x << 5;
    const int by = blockIdx.y << 5;
    const int tx = threadIdx.x & 31;
    const int ty = threadIdx.x >> 5;
#pragma unroll
    for (int i = 0; i < 32; i += 8) {
        int r = by + ty + i, c = bx + tx;
        if (r < R && c < C) t[ty + i][tx] = src[(size_t)r * C + c];
    }
    __syncthreads();
#pragma unroll
    for (int i = 0; i < 32; i += 8) {
        int r = bx + ty + i, c = by + tx;
        if (r < C && c < R) dst[(size_t)r * Rstride + c] = roundtf(t[tx][ty + i]);
    }
}

__global__ __launch_bounds__(256)
void zero_ssm()
{
    size_t i = ((size_t)blockIdx.x * blockDim.x + threadIdx.x) * 4;
    if (i < (size_t)BLn * SP) *(float4*)&g_ssm[i] = make_float4(0.f, 0.f, 0.f, 0.f);
}

__global__ __launch_bounds__(256)
void round_dtraw()
{
    int i = blockIdx.x * blockDim.x + threadIdx.x;   // over BLn*Rn
    if (i >= BLn * Rn) return;
    int row = i / Rn, col = i - row * Rn;
    g_dtraw[(size_t)row * RnP + col] = roundtf(g_ssm[(size_t)row * SP + col]);
}

// ============================================================================
// TF32 mma.sync GEMM: 128x128 CTA, 8 warps of 64x32, BK=32, 3-stage cp.async,
// ldmatrix x4 for both A and B.  C[M,N] = A[M,K](lda) @ Bt[N,K](ldb)^T.
// A,Bt pre-rounded tf32. EPI==1: C = softplus(C + bias[n]).
// smem/stage: (128+128) rows x 36 floats = 36864 B; 3 stages = 110592 B.
// ============================================================================
#define TG_STAGES 3
#define TG_TSZ (128 * 36)                  /* floats per operand tile */
#define TG_STG (2 * TG_TSZ)
#define TG_SMEM (TG_STAGES * TG_STG * 4)   /* 110592 bytes */

template<int EPI>
__global__ __launch_bounds__(256, 2)
void tgemm(const float* __restrict__ A, int lda,
           const float* __restrict__ Bt, int ldb,
           float* __restrict__ C, int N, int K,
           const float* __restrict__ bias)
{
    extern __shared__ float smem[];

    const int tid  = threadIdx.x;
    const int lane = tid & 31;
    const int warp = tid >> 5;
    const int wm   = warp >> 2;        // 0..1
    const int wn   = warp & 3;         // 0..3
    const int m0   = wm * 64;
    const int n0   = wn * 32;
    const int g    = lane >> 2;
    const int c    = lane & 3;

    const int bm = blockIdx.y << 7;
    const int bn = blockIdx.x << 7;

    const uint32_t smem0 = smem_u32(smem);

    // cp.async: per operand tile 1024 chunks of 16B (128 rows x 8 chunks); 4/thread,
    // strided ch = tid + i*256  ->  row = ch>>3, k4 = (ch&7)*4.
    uint32_t sOffA[4];
    const float* ApA[4];
    const float* BpA[4];
#pragma unroll
    for (int i = 0; i < 4; i++) {
        const int ch  = tid + (i << 8);
        const int row = ch >> 3;
        const int k4  = (ch & 7) << 2;
        sOffA[i] = (uint32_t)(row * 36 + k4) * 4;
        ApA[i] = A  + (size_t)(bm + row) * lda + k4;
        BpA[i] = Bt + (size_t)(bn + row) * ldb + k4;
    }

    // ldmatrix bases (stride-36 rows)
    const int arow = m0 + (lane & 7) + ((lane & 8) ? 8 : 0);
    const int acol = (lane & 16) ? 4 : 0;
    const uint32_t aBase = (uint32_t)(arow * 36 + acol) * 4;
    const int brow = n0 + (lane & 7) + ((lane & 16) ? 8 : 0);
    const int bcol = (lane & 8) ? 4 : 0;
    const uint32_t bBase = (uint32_t)(brow * 36 + bcol) * 4;

    float acc[4][4][4];
#pragma unroll
    for (int i = 0; i < 4; i++)
#pragma unroll
        for (int j = 0; j < 4; j++)
#pragma unroll
            for (int q = 0; q < 4; q++) acc[i][j][q] = 0.f;

    const int nk = K >> 5;   // BK = 32

    auto load_stage = [&](int kt, int s) {
        const uint32_t stA = smem0 + (uint32_t)(s * TG_STG) * 4;
        const uint32_t stB = stA + TG_TSZ * 4;
        const int k0 = kt << 5;
#pragma unroll
        for (int i = 0; i < 4; i++) {
            cp16s(stA + sOffA[i], ApA[i] + k0);
            cp16s(stB + sOffA[i], BpA[i] + k0);
        }
    };
    auto compute = [&](int s) {
        const uint32_t stA = smem0 + (uint32_t)(s * TG_STG) * 4;
        const uint32_t stB = stA + TG_TSZ * 4;
#pragma unroll
        for (int ks = 0; ks < 4; ks++) {
            const uint32_t kb = (uint32_t)(ks << 3) * 4;   // k-halves 0,8,16,24
            uint32_t af[4][4], bf[4][2];
#pragma unroll
            for (int i = 0; i < 4; i++)
                ldsm_x4(af[i][0], af[i][1], af[i][2], af[i][3],
                        stA + aBase + (uint32_t)(i * 16 * 36) * 4 + kb);
#pragma unroll
            for (int jj = 0; jj < 2; jj++)
                ldsm_x4(bf[2 * jj][0], bf[2 * jj][1], bf[2 * jj + 1][0], bf[2 * jj + 1][1],
                        stB + bBase + (uint32_t)(jj * 16 * 36) * 4 + kb);
#pragma unroll
            for (int i = 0; i < 4; i++)
#pragma unroll
                for (int j = 0; j < 4; j++)
                    asm volatile(
                        "mma.sync.aligned.m16n8k8.row.col.f32.tf32.tf32.f32 "
                        "{%0,%1,%2,%3}, {%4,%5,%6,%7}, {%8,%9}, {%0,%1,%2,%3};\n"
                        : "+f"(acc[i][j][0]), "+f"(acc[i][j][1]),
                          "+f"(acc[i][j][2]), "+f"(acc[i][j][3])
                        : "r"(af[i][0]), "r"(af[i][1]), "r"(af[i][2]), "r"(af[i][3]),
                          "r"(bf[j][0]), "r"(bf[j][1]));
        }
    };

    // prologue: stages 0,1
#pragma unroll
    for (int s = 0; s < TG_STAGES - 1; s++) {
        if (s < nk) load_stage(s, s);
        cp_commit();
    }
    for (int kt = 0; kt < nk; ++kt) {
        cp_wait<TG_STAGES - 2>();
        __syncthreads();
        const int nxt = kt + TG_STAGES - 1;
        if (nxt < nk) {
            int s = nxt % TG_STAGES;
            load_stage(nxt, s);
        }
        cp_commit();
        compute(kt % TG_STAGES);
    }

    // epilogue
#pragma unroll
    for (int i = 0; i < 4; i++) {
        const int r0 = bm + m0 + i * 16 + g;
#pragma unroll
        for (int j = 0; j < 4; j++) {
            const int col = bn + n0 + j * 8 + 2 * c;
            float v00 = acc[i][j][0], v01 = acc[i][j][1];
            float v10 = acc[i][j][2], v11 = acc[i][j][3];
            if (EPI == 1) {
                const float b0v = bias[col], b1v = bias[col + 1];
                v00 = softplusf_(v00 + b0v);
                v01 = softplusf_(v01 + b1v);
                v10 = softplusf_(v10 + b0v);
                v11 = softplusf_(v11 + b1v);
            }
            *(float2*)&C[(size_t)r0 * N + col]       = make_float2(v00, v01);
            *(float2*)&C[(size_t)(r0 + 8) * N + col] = make_float2(v10, v11);
        }
    }
}

// ============================================================================
// Depthwise causal conv (K=4) + bias + SiLU, 4 channels/thread.
// ============================================================================
__global__ __launch_bounds__(256)
void conv_silu(const float* __restrict__ proj,
               const float* __restrict__ cw,
               const float* __restrict__ cb,
               float* __restrict__ h)
{
    int idx = blockIdx.x * blockDim.x + threadIdx.x;
    int d4 = (idx % (DIn / 4)) << 2;
    int bt = idx / (DIn / 4);
    int t  = bt % Ln;

    const float* p = proj + (size_t)bt * (2 * DIn) + d4;
    const int s = 2 * DIn;
    float4 z  = make_float4(0.f, 0.f, 0.f, 0.f);
    float4 x0 = *(const float4*)p;
    float4 x1 = (t >= 1) ? *(const float4*)(p - s)     : z;
    float4 x2 = (t >= 2) ? *(const float4*)(p - 2 * s) : z;
    float4 x3 = (t >= 3) ? *(const float4*)(p - 3 * s) : z;
    float4 cbv = *(const float4*)(cb + d4);
    float4 w0 = *(const float4*)(cw + (d4 + 0) * 4);
    float4 w1 = *(const float4*)(cw + (d4 + 1) * 4);
    float4 w2 = *(const float4*)(cw + (d4 + 2) * 4);
    float4 w3 = *(const float4*)(cw + (d4 + 3) * 4);

    float4 o;
    o.x = fmaf(x3.x, w0.x, fmaf(x2.x, w0.y, fmaf(x1.x, w0.z, fmaf(x0.x, w0.w, cbv.x))));
    o.y = fmaf(x3.y, w1.x, fmaf(x2.y, w1.y, fmaf(x1.y, w1.z, fmaf(x0.y, w1.w, cbv.y))));
    o.z = fmaf(x3.z, w2.x, fmaf(x2.z, w2.y, fmaf(x1.z, w2.z, fmaf(x0.z, w2.w, cbv.z))));
    o.w = fmaf(x3.w, w3.x, fmaf(x2.w, w3.y, fmaf(x1.w, w3.z, fmaf(x0.w, w3.w, cbv.w))));
    o.x = o.x * sigmoidf_(o.x);
    o.y = o.y * sigmoidf_(o.y);
    o.z = o.z * sigmoidf_(o.z);
    o.w = o.w * sigmoidf_(o.w);
    *(float4*)(h + (size_t)bt * DIn + d4) = o;
}

// ============================================================================
// x_proj GEMM, split-K: ssm += h @ x_proj_w.
// ============================================================================
#define XKS 4
#define XKC (DIn / XKS)
__global__ __launch_bounds__(256)
void gemm_xproj(const float* __restrict__ A,
                const float* __restrict__ W)
{
    __shared__ float As[2][16][68];
    __shared__ float Ws[2][16][SP];

    const int tid = threadIdx.x;
    const int bm  = blockIdx.x << 6;
    const int k0  = blockIdx.y * XKC;
    const int tx  = tid & 15;
    const int ty  = tid >> 4;
    const int ar  = tid >> 2;
    const int ac4 = (tid & 3) << 2;

    float acc[4][5];
#pragma unroll
    for (int i = 0; i < 4; i++)
#pragma unroll
        for (int j = 0; j < 5; j++) acc[i][j] = 0.f;

    const float* Ap = A + (size_t)(bm + ar) * DIn + k0 + ac4;
    const int nk = XKC / 16;

    float4 aR; float wR[5];
    auto g2r = [&](int kt) {
        aR = *(const float4*)(Ap + kt * 16);
#pragma unroll
        for (int j = 0; j < 5; j++) {
            int e = tid + (j << 8);
            int k = e / SP, n2 = e % SP;
            wR[j] = W[(size_t)(k0 + kt * 16 + k) * SP + n2];
        }
    };
    auto r2s = [&](int buf) {
        As[buf][ac4 + 0][ar] = aR.x;
        As[buf][ac4 + 1][ar] = aR.y;
        As[buf][ac4 + 2][ar] = aR.z;
        As[buf][ac4 + 3][ar] = aR.w;
#pragma unroll
        for (int j = 0; j < 5; j++) {
            int e = tid + (j << 8);
            int k = e / SP, n2 = e % SP;
            Ws[buf][k][n2] = wR[j];
        }
    };

    g2r(0); r2s(0);
    __syncthreads();

    for (int kt = 0; kt < nk; ++kt) {
        const int buf = kt & 1;
        const bool more = (kt + 1 < nk);
        if (more) g2r(kt + 1);
#pragma unroll
        for (int k = 0; k < 16; k++) {
            float4 a4 = *(const float4*)&As[buf][k][ty << 2];
            float av[4] = {a4.x, a4.y, a4.z, a4.w};
#pragma unroll
            for (int j = 0; j < 5; j++) {
                float w = Ws[buf][k][tx * 5 + j];
#pragma unroll
                for (int i = 0; i < 4; i++)
                    acc[i][j] = fmaf(av[i], w, acc[i][j]);
            }
        }
        if (more) r2s(buf ^ 1);
        __syncthreads();
    }

#pragma unroll
    for (int i = 0; i < 4; i++) {
        const int row = bm + (ty << 2) + i;
#pragma unroll
        for (int j = 0; j < 5; j++)
            atomicAdd(&g_ssm[(size_t)row * SP + tx * 5 + j], acc[i][j]);
    }
}

// ============================================================================
// Fused selective scan + skip + gating. 8-timestep batched shuffle reduction.
// ============================================================================
__global__ __launch_bounds__(128)
void scan_kernel(const float* __restrict__ Alog, const float* __restrict__ Dp)
{
    __shared__ float s_h [2][32][8];
    __shared__ float s_dt[2][32][8];
    __shared__ float s_g [2][32][8];
    __shared__ float s_B [2][32][16];
    __shared__ float s_C [2][32][16];

    const int tid  = threadIdx.x;
    const int lane = tid & 31;
    const int w    = tid >> 5;
    const int n    = lane & 15;
    const int half = lane >> 4;
    const int dl   = (w << 1) + half;
    const int blk  = blockIdx.x;
    const int b    = blk / (DIn / 8);
    const int d0   = (blk % (DIn / 8)) << 3;
    const int d    = d0 + dl;
    const int bL   = b * Ln;

    const float A_dn = -__expf(Alog[d * Nn + n]);
    const float Dv   = Dp[d];
    float state = 0.f;

    float rh[2], rdt[2], rg[2], rB[4], rC[4];

    auto do_load = [&](int c) {
        int t0 = c << 5;
#pragma unroll
        for (int j = 0; j < 2; j++) {
            int e = tid + (j << 7);
            int t = e >> 3, dd = e & 7;
            int row = bL + t0 + t;
            rh[j]  = g_h [(size_t)row * DIn + d0 + dd];
            rdt[j] = g_dt[(size_t)row * DIn + d0 + dd];
            rg[j]  = g_proj[(size_t)row * (2 * DIn) + DIn + d0 + dd];
        }
#pragma unroll
        for (int j = 0; j < 4; j++) {
            int e = tid + (j << 7);
            int t = e >> 4, nn = e & 15;
            int row = bL + t0 + t;
            rB[j] = g_ssm[(size_t)row * SP + Rn + nn];
            rC[j] = g_ssm[(size_t)row * SP + Rn + Nn + nn];
        }
    };
    auto do_store = [&](int buf) {
#pragma unroll
        for (int j = 0; j < 2; j++) {
            int e = tid + (j << 7);
            int t = e >> 3, dd = e & 7;
            s_h [buf][t][dd] = rh[j];
            s_dt[buf][t][dd] = rdt[j];
            s_g [buf][t][dd] = rg[j];
        }
#pragma unroll
        for (int j = 0; j < 4; j++) {
            int e = tid + (j << 7);
            int t = e >> 4, nn = e & 15;
            s_B[buf][t][nn] = rB[j];
            s_C[buf][t][nn] = rC[j];
        }
    };

    do_load(0);
    do_store(0);
    __syncthreads();

    const int NC = Ln / 32;
    for (int c = 0; c < NC; c++) {
        const int buf = c & 1;
        if (c + 1 < NC) do_load(c + 1);
        const int t0 = c << 5;
#pragma unroll
        for (int tb = 0; tb < 32; tb += 8) {
            float p[8], hs[8];
#pragma unroll
            for (int tt = 0; tt < 8; tt++) {
                const int t = tb + tt;
                float dtv = s_dt[buf][t][dl];
                float hv  = s_h [buf][t][dl];
                float Bv  = s_B [buf][t][n];
                float Cv  = s_C [buf][t][n];
                float dA  = __expf(A_dn * dtv);
                state = fmaf(dA, state, Bv * hv);
                p[tt]  = state * Cv;
                hs[tt] = hv;
            }
#pragma unroll
            for (int st = 8; st >= 1; st >>= 1)
#pragma unroll
                for (int tt = 0; tt < 8; tt++)
                    p[tt] += __shfl_xor_sync(0xffffffffu, p[tt], st);
            if (n == 0) {
#pragma unroll
                for (int tt = 0; tt < 8; tt++) {
                    const int t = tb + tt;
                    float gv = s_g[buf][t][dl];
                    float yv = (p[tt] + hs[tt] * Dv) * gv * sigmoidf_(gv);
                    g_y[(size_t)(bL + t0 + t) * DIn + d] = roundtf(yv);
                }
            }
        }
        if (c + 1 < NC) do_store(buf ^ 1);
        __syncthreads();
    }
}

// ============================================================================
extern "C" void kernel_launch(void* const* d_in, const int* in_sizes, int n_in,
                              void* d_out, int out_size)
{
    const float* x          = (const float*)d_in[0];
    const float* in_proj_w  = (const float*)d_in[1];
    const float* conv_w     = (const float*)d_in[2];
    const float* conv_b     = (const float*)d_in[3];
    const float* x_proj_w   = (const float*)d_in[4];
    const float* dt_proj_w  = (const float*)d_in[5];
    const float* dt_proj_b  = (const float*)d_in[6];
    const float* out_proj_w = (const float*)d_in[7];
    const float* A_log      = (const float*)d_in[8];
    const float* D_param    = (const float*)d_in[9];
    float* out = (float*)d_out;

    float *proj, *h, *dtraw, *dt, *y, *xr, *w1t, *w2t, *w3t;
    cudaGetSymbolAddress((void**)&proj,  g_proj);
    cudaGetSymbolAddress((void**)&h,     g_h);
    cudaGetSymbolAddress((void**)&dtraw, g_dtraw);
    cudaGetSymbolAddress((void**)&dt,    g_dt);
    cudaGetSymbolAddress((void**)&y,     g_y);
    cudaGetSymbolAddress((void**)&xr,    g_xr);
    cudaGetSymbolAddress((void**)&w1t,   g_w1);
    cudaGetSymbolAddress((void**)&w2t,   g_w2);
    cudaGetSymbolAddress((void**)&w3t,   g_w3);

    cudaFuncSetAttribute(tgemm<0>, cudaFuncAttributeMaxDynamicSharedMemorySize, TG_SMEM);
    cudaFuncSetAttribute(tgemm<1>, cudaFuncAttributeMaxDynamicSharedMemorySize, TG_SMEM);

    // 0) pre-round x; transpose+round w1, w2 (K-padded), w3; zero split-K acc
    preround<<<(unsigned)((S0 / 4 + 255) / 256), 256>>>(x);
    transpose_round<<<dim3((2 * DIn) / 32, Hn / 32), 256>>>(in_proj_w,  w1t, Hn, 2 * DIn, Hn);
    transpose_round<<<dim3(DIn / 32, (Rn + 31) / 32), 256>>>(dt_proj_w, w2t, Rn, DIn, RnP);
    transpose_round<<<dim3(Hn / 32, DIn / 32), 256>>>(out_proj_w, w3t, DIn, Hn, DIn);
    zero_ssm<<<(BLn * SP / 4 + 255) / 256, 256>>>();

    // 1) proj = x @ in_proj_w   [4096,3072], K=768
    tgemm<0><<<dim3((2 * DIn) / 128, BLn / 128), 256, TG_SMEM>>>(
        xr, Hn, w1t, Hn, proj, 2 * DIn, Hn, nullptr);

    // 2) depthwise causal conv + SiLU -> g_h
    conv_silu<<<(BLn * DIn / 4) / 256, 256>>>(proj, conv_w, conv_b, h);

    // 3) ssm += h @ x_proj_w   [4096,80] split-K
    gemm_xproj<<<dim3(BLn / 64, XKS), 256>>>(h, x_proj_w);
    round_dtraw<<<(BLn * Rn + 255) / 256, 256>>>();

    // 4) dt = softplus(dt_raw @ dt_proj_w + b)   [4096,1536], K=64 (zero-padded)
    tgemm<1><<<dim3(DIn / 128, BLn / 128), 256, TG_SMEM>>>(
        dtraw, RnP, w2t, RnP, dt, DIn, RnP, dt_proj_b);

    // 5) selective scan (+ skip + gating)
    scan_kernel<<<Bn * (DIn / 8), 128>>>(A_log, D_param);

    // 6) out = y @ out_proj_w   [4096,768], K=1536
    tgemm<0><<<dim3(Hn / 128, BLn / 128), 256, TG_SMEM>>>(
        y, DIn, w3t, DIn, out, Hn, DIn, nullptr);
}